// round 1
// baseline (speedup 1.0000x reference)
#include <cuda_runtime.h>

#define BS 8
#define NA 8400
#define NM 128
#define NC 80
#define TOPK 13
#define EPSF 1e-9f

// Scratch (no allocations allowed)
__device__ int   g_count[BS * NA];
__device__ int   g_am[BS * NA];
__device__ float g_cls[BS * NA];

// ---------------------------------------------------------------------------
// K1: per-anchor class argmax (first-max tie rule) + scratch init
// ---------------------------------------------------------------------------
__global__ void k_argmax_init(const float* __restrict__ pd_scores) {
    int idx = blockIdx.x * blockDim.x + threadIdx.x;
    if (idx >= BS * NA) return;
    const float4* p = (const float4*)(pd_scores + (size_t)idx * NC);
    float best = -3.0e38f;
    int bc = 0;
#pragma unroll
    for (int i = 0; i < NC / 4; ++i) {
        float4 v = p[i];
        if (v.x > best) { best = v.x; bc = i * 4 + 0; }
        if (v.y > best) { best = v.y; bc = i * 4 + 1; }
        if (v.z > best) { best = v.z; bc = i * 4 + 2; }
        if (v.w > best) { best = v.w; bc = i * 4 + 3; }
    }
    g_cls[idx]   = (float)bc;
    g_count[idx] = 0;
    g_am[idx]    = 0x7FFFFFFF;
}

// ---------------------------------------------------------------------------
// K2: per-(b,m) top-13 of align over anchors; count + argmin-m bookkeeping.
// Key packing: (align_bits << 32) | ~anchor  -> larger key == (bigger value,
// then smaller anchor index), matching jax.lax.top_k tie semantics.
// ---------------------------------------------------------------------------
__global__ void k_topk(const float* __restrict__ pd_boxes,
                       const float* __restrict__ gt_boxes,
                       const float* __restrict__ mask_gt) {
    __shared__ unsigned long long s_lists[256 * TOPK];
    __shared__ unsigned long long s_red[256];
    __shared__ int s_tid[256];

    int bm = blockIdx.x;
    int b = bm / NM;
    int m = bm - b * NM;
    int tid = threadIdx.x;

    float mg = mask_gt[bm];
    if (mg == 0.0f) {
        // align is all-zero: top-13 = anchors 0..12 (tie -> lowest index)
        if (tid < TOPK) {
            atomicAdd(&g_count[b * NA + tid], 1);
            atomicMin(&g_am[b * NA + tid], m);
        }
        return;
    }

    float4 g = ((const float4*)gt_boxes)[bm];
    float area_g = (g.z - g.x) * (g.w - g.y);
    const float4* pb = (const float4*)pd_boxes + (size_t)b * NA;
    const float* cl = g_cls + (size_t)b * NA;

    unsigned long long lst[TOPK];
#pragma unroll
    for (int i = 0; i < TOPK; ++i) lst[i] = 0ULL;

    for (int a = tid; a < NA; a += 256) {
        float4 p = pb[a];
        float lx = fmaxf(g.x, p.x), ly = fmaxf(g.y, p.y);
        float rx = fminf(g.z, p.z), ry = fminf(g.w, p.w);
        float iw = fmaxf(rx - lx, 0.0f), ih = fmaxf(ry - ly, 0.0f);
        float inter = iw * ih;
        float area_p = (p.z - p.x) * (p.w - p.y);
        float iou = inter / (area_g + area_p - inter + EPSF);
        float cx = (p.x + p.z) * 0.5f, cy = (p.y + p.w) * 0.5f;
        float dmin = fminf(fminf(cx - g.x, cy - g.y), fminf(g.z - cx, g.w - cy));
        float al = 0.0f;
        if (dmin > EPSF) {
            float i2 = iou * iou;
            al = cl[a] * ((i2 * i2) * i2);   // x^6 = (x^2)^2 * x^2, XLA-style
        }
        unsigned long long key =
            ((unsigned long long)__float_as_uint(al) << 32) |
            (unsigned int)(~(unsigned int)a);
        if (key > lst[TOPK - 1]) {
            lst[TOPK - 1] = key;
#pragma unroll
            for (int j = TOPK - 1; j > 0; --j) {
                if (lst[j] > lst[j - 1]) {
                    unsigned long long t = lst[j - 1];
                    lst[j - 1] = lst[j];
                    lst[j] = t;
                }
            }
        }
    }

#pragma unroll
    for (int i = 0; i < TOPK; ++i) s_lists[tid * TOPK + i] = lst[i];

    int ptr = 0;
    for (int r = 0; r < TOPK; ++r) {
        s_red[tid] = s_lists[tid * TOPK + ptr];  // ptr <= r <= 12, in bounds
        s_tid[tid] = tid;
        __syncthreads();
        for (int off = 128; off > 0; off >>= 1) {
            if (tid < off && s_red[tid + off] > s_red[tid]) {
                s_red[tid] = s_red[tid + off];
                s_tid[tid] = s_tid[tid + off];
            }
            __syncthreads();
        }
        if (tid == 0) {
            unsigned int a = ~(unsigned int)(s_red[0] & 0xFFFFFFFFULL);
            atomicAdd(&g_count[b * NA + a], 1);
            atomicMin(&g_am[b * NA + a], m);
        }
        int w = s_tid[0];
        __syncthreads();
        if (tid == w) ptr++;
    }
}

// ---------------------------------------------------------------------------
// K3: per-anchor conflict resolution + output emission.
// Outputs concatenated in tuple order (tl, tb, ts, mask), all f32.
// ---------------------------------------------------------------------------
__global__ void k_out(const float* __restrict__ pd_boxes,
                      const int* __restrict__ gt_labels,
                      const float* __restrict__ gt_boxes,
                      float* __restrict__ out) {
    int idx = blockIdx.x * blockDim.x + threadIdx.x;
    if (idx >= BS * NA) return;
    int b = idx / NA;

    int c = g_count[idx];
    int am = 0;
    float msk = 0.0f;
    if (c == 1) {
        am = g_am[idx];
        msk = 1.0f;
    } else if (c > 1) {
        // multi-assigned anchor: argmax IoU over ALL gts (first m on ties)
        float4 p = ((const float4*)pd_boxes)[idx];
        float area_p = (p.z - p.x) * (p.w - p.y);
        const float4* gb = (const float4*)gt_boxes + (size_t)b * NM;
        float best = -1.0f;
        for (int mm = 0; mm < NM; ++mm) {
            float4 g = gb[mm];
            float lx = fmaxf(g.x, p.x), ly = fmaxf(g.y, p.y);
            float rx = fminf(g.z, p.z), ry = fminf(g.w, p.w);
            float iw = fmaxf(rx - lx, 0.0f), ih = fmaxf(ry - ly, 0.0f);
            float inter = iw * ih;
            float area_g = (g.z - g.x) * (g.w - g.y);
            float iou = inter / (area_g + area_p - inter + EPSF);
            if (iou > best) { best = iou; am = mm; }
        }
        msk = 1.0f;
    }

    int lbl = (msk > 0.0f) ? gt_labels[b * NM + am] : NC;

    float* tl = out;
    float* tb = out + (size_t)BS * NA;
    float* ts = out + (size_t)BS * NA * 5;
    float* mo = out + (size_t)BS * NA * 85;

    tl[idx] = (float)lbl;
    ((float4*)tb)[idx] = ((const float4*)gt_boxes)[b * NM + am];
    float4* tsp = (float4*)(ts + (size_t)idx * NC);
#pragma unroll
    for (int i = 0; i < NC / 4; ++i) tsp[i] = make_float4(0.f, 0.f, 0.f, 0.f);
    if (lbl < NC) ts[(size_t)idx * NC + lbl] = 1.0f;
    mo[idx] = msk;
}

// ---------------------------------------------------------------------------
extern "C" void kernel_launch(void* const* d_in, const int* in_sizes, int n_in,
                              void* d_out, int out_size) {
    const float* pd_scores = (const float*)d_in[0];
    const float* pd_boxes  = (const float*)d_in[1];
    const int*   gt_labels = (const int*)d_in[2];
    const float* gt_boxes  = (const float*)d_in[3];
    const float* mask_gt   = (const float*)d_in[4];
    float* out = (float*)d_out;

    int n = BS * NA;
    k_argmax_init<<<(n + 255) / 256, 256>>>(pd_scores);
    k_topk<<<BS * NM, 256>>>(pd_boxes, gt_boxes, mask_gt);
    k_out<<<(n + 255) / 256, 256>>>(pd_boxes, gt_labels, gt_boxes, out);
}

// round 3
// speedup vs baseline: 1.5439x; 1.5439x over previous
#include <cuda_runtime.h>

#define BS 8
#define NA 8400
#define NM 128
#define NC 80
#define TOPK 13
#define EPSF 1e-9f

#define G 8          // gts per k_topk block
#define MAXPOS 640   // per-gt positive-candidate buffer cap (8-sigma margin)

typedef unsigned long long ull;

// Scratch (no allocations allowed)
__device__ int   g_count[BS * NA];
__device__ int   g_am[BS * NA];
__device__ float g_cls[BS * NA];

// ---------------------------------------------------------------------------
// K1: warp-per-anchor class argmax (coalesced), + scratch init.
// Packed key: (orderable_float << 32) | ~class  -> max == (bigger score,
// then lower class index), matching jnp.argmax first-max semantics.
// ---------------------------------------------------------------------------
__global__ void k_argmax_init(const float* __restrict__ pd_scores) {
    int wid = threadIdx.x >> 5;
    int lane = threadIdx.x & 31;
    int anchor = blockIdx.x * 8 + wid;
    if (anchor >= BS * NA) return;
    const float* row = pd_scores + (size_t)anchor * NC;

    ull best = 0;
#pragma unroll
    for (int i = 0; i < 3; ++i) {
        int c = lane + i * 32;
        if (c < NC) {
            unsigned bits = __float_as_uint(row[c]);
            unsigned u = (bits & 0x80000000u) ? ~bits : (bits | 0x80000000u);
            ull key = ((ull)u << 32) | (unsigned)(~c);
            if (key > best) best = key;
        }
    }
#pragma unroll
    for (int off = 16; off > 0; off >>= 1) {
        ull o = __shfl_xor_sync(0xFFFFFFFFu, best, off);
        if (o > best) best = o;
    }
    if (lane == 0) g_cls[anchor] = (float)(~(unsigned)(best & 0xFFFFFFFFull));
    if (threadIdx.x < 8) {
        int a2 = blockIdx.x * 8 + threadIdx.x;
        if (a2 < BS * NA) { g_count[a2] = 0; g_am[a2] = 0x7FFFFFFF; }
    }
}

// ---------------------------------------------------------------------------
// K2: one block per (b, group of G gts). Phase 1 collects anchors with
// align > 0 into per-gt shared buffers. Phase 2: one warp per gt extracts
// top-13 (value desc, index asc) and updates count/am; fills with lowest-
// index zero-align anchors when fewer than 13 positives exist.
// ---------------------------------------------------------------------------
__global__ __launch_bounds__(512) void k_topk(const float* __restrict__ pd_boxes,
                                              const float* __restrict__ gt_boxes,
                                              const float* __restrict__ mask_gt) {
    __shared__ int  sn[G];
    __shared__ ull  keys[G][MAXPOS];
    __shared__ unsigned selbuf[G][TOPK];
    __shared__ float4 sg[G];
    __shared__ float  smk[G];

    int b = blockIdx.x / (NM / G);
    int mbase = (blockIdx.x % (NM / G)) * G;
    int tid = threadIdx.x;

    if (tid < G) {
        sn[tid] = 0;
        sg[tid] = ((const float4*)gt_boxes)[b * NM + mbase + tid];
        smk[tid] = mask_gt[b * NM + mbase + tid];
    }
    __syncthreads();

    // hoist gt data into registers
    float4 gr[G]; float ga[G]; bool act[G];
#pragma unroll
    for (int w = 0; w < G; ++w) {
        gr[w] = sg[w];
        ga[w] = (gr[w].z - gr[w].x) * (gr[w].w - gr[w].y);
        act[w] = (smk[w] != 0.0f);
    }

    const float4* pb = (const float4*)pd_boxes + (size_t)b * NA;
    const float*  cl = g_cls + (size_t)b * NA;

    for (int a = tid; a < NA; a += 512) {
        float4 p = __ldg(&pb[a]);
        float c = __ldg(&cl[a]);
        float area_p = (p.z - p.x) * (p.w - p.y);
        float cx = (p.x + p.z) * 0.5f, cy = (p.y + p.w) * 0.5f;
#pragma unroll
        for (int w = 0; w < G; ++w) {
            if (!act[w]) continue;
            float4 g = gr[w];
            float dmin = fminf(fminf(cx - g.x, cy - g.y), fminf(g.z - cx, g.w - cy));
            if (dmin > EPSF && c > 0.0f) {
                float lx = fmaxf(g.x, p.x), ly = fmaxf(g.y, p.y);
                float rx = fminf(g.z, p.z), ry = fminf(g.w, p.w);
                float iw = fmaxf(rx - lx, 0.0f), ih = fmaxf(ry - ly, 0.0f);
                float inter = iw * ih;
                float iou = inter / (ga[w] + area_p - inter + EPSF);
                float i2 = iou * iou;
                float al = c * ((i2 * i2) * i2);
                if (al > 0.0f) {
                    int pos = atomicAdd(&sn[w], 1);
                    if (pos < MAXPOS) {
                        keys[w][pos] = ((ull)__float_as_uint(al) << 32) |
                                       (unsigned)(~(unsigned)a);
                    }
                }
            }
        }
    }
    __syncthreads();

    int wid = tid >> 5, lane = tid & 31;
    if (wid < G) {
        int m = mbase + wid;
        if (!act[wid]) {
            // align all zero: top-13 = anchors 0..12
            if (lane < TOPK) {
                atomicAdd(&g_count[b * NA + lane], 1);
                atomicMin(&g_am[b * NA + lane], m);
            }
        } else {
            int n = min(sn[wid], MAXPOS);
            ull* K = keys[wid];
            int sel = min(n, TOPK);
            for (int r = 0; r < sel; ++r) {
                ull bk = 0; int bp = -1;
                for (int i = lane; i < n; i += 32) {
                    ull k = K[i];
                    if (k > bk) { bk = k; bp = i; }
                }
#pragma unroll
                for (int off = 16; off > 0; off >>= 1) {
                    ull ok = __shfl_xor_sync(0xFFFFFFFFu, bk, off);
                    int op = __shfl_xor_sync(0xFFFFFFFFu, bp, off);
                    if (ok > bk) { bk = ok; bp = op; }
                }
                if (lane == 0) {
                    unsigned aa = ~(unsigned)(bk & 0xFFFFFFFFull);
                    selbuf[wid][r] = aa;
                    atomicAdd(&g_count[b * NA + aa], 1);
                    atomicMin(&g_am[b * NA + aa], m);
                    K[bp] = 0;
                }
                __syncwarp();
            }
            __syncwarp();
            if (lane == 0 && n < TOPK) {
                // fill with lowest-index zero-align anchors (all positives are
                // in selbuf[0..n) in this branch)
                int f = TOPK - n;
                for (int a = 0; f > 0; ++a) {
                    bool pos = false;
                    for (int i = 0; i < n; ++i)
                        if (selbuf[wid][i] == (unsigned)a) { pos = true; break; }
                    if (!pos) {
                        atomicAdd(&g_count[b * NA + a], 1);
                        atomicMin(&g_am[b * NA + a], m);
                        --f;
                    }
                }
            }
        }
    }
}

// ---------------------------------------------------------------------------
// K3a: coalesced zero-fill of the ts (one-hot) region.
// ---------------------------------------------------------------------------
__global__ void k_fill(float* __restrict__ out) {
    size_t i = (size_t)blockIdx.x * blockDim.x + threadIdx.x;
    size_t n4 = (size_t)BS * NA * NC / 4;
    if (i < n4) {
        ((float4*)(out + (size_t)BS * NA * 5))[i] = make_float4(0.f, 0.f, 0.f, 0.f);
    }
}

// ---------------------------------------------------------------------------
// K3b: per-anchor conflict resolution + output emission (tl, tb, one-hot
// scatter, mask). Outputs in tuple order, all f32.
// ---------------------------------------------------------------------------
__global__ void k_out(const float* __restrict__ pd_boxes,
                      const int* __restrict__ gt_labels,
                      const float* __restrict__ gt_boxes,
                      float* __restrict__ out) {
    int idx = blockIdx.x * blockDim.x + threadIdx.x;
    if (idx >= BS * NA) return;
    int b = idx / NA;

    int c = g_count[idx];
    int am = 0;
    float msk = 0.0f;
    if (c == 1) {
        am = g_am[idx];
        msk = 1.0f;
    } else if (c > 1) {
        // multi-assigned anchor: argmax IoU over ALL gts (first m on ties)
        float4 p = ((const float4*)pd_boxes)[idx];
        float area_p = (p.z - p.x) * (p.w - p.y);
        const float4* gb = (const float4*)gt_boxes + (size_t)b * NM;
        float best = -1.0f;
        for (int mm = 0; mm < NM; ++mm) {
            float4 g = gb[mm];
            float lx = fmaxf(g.x, p.x), ly = fmaxf(g.y, p.y);
            float rx = fminf(g.z, p.z), ry = fminf(g.w, p.w);
            float iw = fmaxf(rx - lx, 0.0f), ih = fmaxf(ry - ly, 0.0f);
            float inter = iw * ih;
            float area_g = (g.z - g.x) * (g.w - g.y);
            float iou = inter / (area_g + area_p - inter + EPSF);
            if (iou > best) { best = iou; am = mm; }
        }
        msk = 1.0f;
    }

    int lbl = (msk > 0.0f) ? gt_labels[b * NM + am] : NC;

    float* tl = out;
    float* tb = out + (size_t)BS * NA;
    float* ts = out + (size_t)BS * NA * 5;
    float* mo = out + (size_t)BS * NA * 85;

    tl[idx] = (float)lbl;
    ((float4*)tb)[idx] = ((const float4*)gt_boxes)[b * NM + am];
    if (lbl < NC) ts[(size_t)idx * NC + lbl] = 1.0f;
    mo[idx] = msk;
}

// ---------------------------------------------------------------------------
extern "C" void kernel_launch(void* const* d_in, const int* in_sizes, int n_in,
                              void* d_out, int out_size) {
    const float* pd_scores = (const float*)d_in[0];
    const float* pd_boxes  = (const float*)d_in[1];
    const int*   gt_labels = (const int*)d_in[2];
    const float* gt_boxes  = (const float*)d_in[3];
    const float* mask_gt   = (const float*)d_in[4];
    float* out = (float*)d_out;

    int n = BS * NA;
    k_argmax_init<<<(n + 7) / 8, 256>>>(pd_scores);
    k_topk<<<BS * NM / G, 512>>>(pd_boxes, gt_boxes, mask_gt);
    int n4 = BS * NA * NC / 4;
    k_fill<<<(n4 + 255) / 256, 256>>>(out);
    k_out<<<(n + 255) / 256, 256>>>(pd_boxes, gt_labels, gt_boxes, out);
}

// round 4
// speedup vs baseline: 2.4371x; 1.5785x over previous
#include <cuda_runtime.h>

#define BS 8
#define NA 8400
#define NM 128
#define NC 80
#define TOPK 13
#define EPSF 1e-9f

#define G 8          // gts per k_topk block
#define MAXPOS 640   // per-gt positive-candidate buffer cap (8-sigma margin)
#define MAXMULTI 7168

typedef unsigned long long ull;

// Scratch (no allocations allowed)
__device__ int   g_count[BS * NA];
__device__ int   g_am[BS * NA];
__device__ float g_cls[BS * NA];
__device__ int   g_wcount;
__device__ int   g_wlist[MAXMULTI];

// ---------------------------------------------------------------------------
// K1: warp-per-anchor class argmax (coalesced), + scratch init.
// ---------------------------------------------------------------------------
__global__ void k_argmax_init(const float* __restrict__ pd_scores) {
    int wid = threadIdx.x >> 5;
    int lane = threadIdx.x & 31;
    int anchor = blockIdx.x * 8 + wid;
    if (blockIdx.x == 0 && threadIdx.x == 0) g_wcount = 0;
    if (anchor >= BS * NA) return;
    const float* row = pd_scores + (size_t)anchor * NC;

    ull best = 0;
#pragma unroll
    for (int i = 0; i < 3; ++i) {
        int c = lane + i * 32;
        if (c < NC) {
            unsigned bits = __float_as_uint(row[c]);
            unsigned u = (bits & 0x80000000u) ? ~bits : (bits | 0x80000000u);
            ull key = ((ull)u << 32) | (unsigned)(~c);
            if (key > best) best = key;
        }
    }
#pragma unroll
    for (int off = 16; off > 0; off >>= 1) {
        ull o = __shfl_xor_sync(0xFFFFFFFFu, best, off);
        if (o > best) best = o;
    }
    if (lane == 0) g_cls[anchor] = (float)(~(unsigned)(best & 0xFFFFFFFFull));
    if (threadIdx.x < 8) {
        int a2 = blockIdx.x * 8 + threadIdx.x;
        if (a2 < BS * NA) { g_count[a2] = 0; g_am[a2] = 0x7FFFFFFF; }
    }
}

// ---------------------------------------------------------------------------
// K2: one block per (b, group of G gts). Phase 1 collects anchors with
// align > 0 into per-gt shared buffers. Phase 2: one warp per gt extracts
// top-13 (value desc, index asc) and updates count/am.
// ---------------------------------------------------------------------------
__global__ __launch_bounds__(512) void k_topk(const float* __restrict__ pd_boxes,
                                              const float* __restrict__ gt_boxes,
                                              const float* __restrict__ mask_gt) {
    __shared__ int  sn[G];
    __shared__ ull  keys[G][MAXPOS];
    __shared__ unsigned selbuf[G][TOPK];
    __shared__ float4 sg[G];
    __shared__ float  smk[G];

    int b = blockIdx.x / (NM / G);
    int mbase = (blockIdx.x % (NM / G)) * G;
    int tid = threadIdx.x;

    if (tid < G) {
        sn[tid] = 0;
        sg[tid] = ((const float4*)gt_boxes)[b * NM + mbase + tid];
        smk[tid] = mask_gt[b * NM + mbase + tid];
    }
    __syncthreads();

    float4 gr[G]; float ga[G]; bool act[G];
#pragma unroll
    for (int w = 0; w < G; ++w) {
        gr[w] = sg[w];
        ga[w] = (gr[w].z - gr[w].x) * (gr[w].w - gr[w].y);
        act[w] = (smk[w] != 0.0f);
    }

    const float4* pb = (const float4*)pd_boxes + (size_t)b * NA;
    const float*  cl = g_cls + (size_t)b * NA;

    for (int a = tid; a < NA; a += 512) {
        float4 p = __ldg(&pb[a]);
        float c = __ldg(&cl[a]);
        float area_p = (p.z - p.x) * (p.w - p.y);
        float cx = (p.x + p.z) * 0.5f, cy = (p.y + p.w) * 0.5f;
#pragma unroll
        for (int w = 0; w < G; ++w) {
            if (!act[w]) continue;
            float4 g = gr[w];
            float dmin = fminf(fminf(cx - g.x, cy - g.y), fminf(g.z - cx, g.w - cy));
            if (dmin > EPSF && c > 0.0f) {
                float lx = fmaxf(g.x, p.x), ly = fmaxf(g.y, p.y);
                float rx = fminf(g.z, p.z), ry = fminf(g.w, p.w);
                float iw = fmaxf(rx - lx, 0.0f), ih = fmaxf(ry - ly, 0.0f);
                float inter = iw * ih;
                float iou = inter / (ga[w] + area_p - inter + EPSF);
                float i2 = iou * iou;
                float al = c * ((i2 * i2) * i2);
                if (al > 0.0f) {
                    int pos = atomicAdd(&sn[w], 1);
                    if (pos < MAXPOS) {
                        keys[w][pos] = ((ull)__float_as_uint(al) << 32) |
                                       (unsigned)(~(unsigned)a);
                    }
                }
            }
        }
    }
    __syncthreads();

    int wid = tid >> 5, lane = tid & 31;
    if (wid < G) {
        int m = mbase + wid;
        if (!act[wid]) {
            if (lane < TOPK) {
                atomicAdd(&g_count[b * NA + lane], 1);
                atomicMin(&g_am[b * NA + lane], m);
            }
        } else {
            int n = min(sn[wid], MAXPOS);
            ull* K = keys[wid];
            int sel = min(n, TOPK);
            for (int r = 0; r < sel; ++r) {
                ull bk = 0; int bp = -1;
                for (int i = lane; i < n; i += 32) {
                    ull k = K[i];
                    if (k > bk) { bk = k; bp = i; }
                }
#pragma unroll
                for (int off = 16; off > 0; off >>= 1) {
                    ull ok = __shfl_xor_sync(0xFFFFFFFFu, bk, off);
                    int op = __shfl_xor_sync(0xFFFFFFFFu, bp, off);
                    if (ok > bk) { bk = ok; bp = op; }
                }
                if (lane == 0) {
                    unsigned aa = ~(unsigned)(bk & 0xFFFFFFFFull);
                    selbuf[wid][r] = aa;
                    atomicAdd(&g_count[b * NA + aa], 1);
                    atomicMin(&g_am[b * NA + aa], m);
                    K[bp] = 0;
                }
                __syncwarp();
            }
            __syncwarp();
            if (lane == 0 && n < TOPK) {
                int f = TOPK - n;
                for (int a = 0; f > 0; ++a) {
                    bool pos = false;
                    for (int i = 0; i < n; ++i)
                        if (selbuf[wid][i] == (unsigned)a) { pos = true; break; }
                    if (!pos) {
                        atomicAdd(&g_count[b * NA + a], 1);
                        atomicMin(&g_am[b * NA + a], m);
                        --f;
                    }
                }
            }
        }
    }
}

// ---------------------------------------------------------------------------
// K3a: coalesced zero-fill of the ts (one-hot) region.
// ---------------------------------------------------------------------------
__global__ void k_fill(float* __restrict__ out) {
    size_t i = (size_t)blockIdx.x * blockDim.x + threadIdx.x;
    size_t n4 = (size_t)BS * NA * NC / 4;
    if (i < n4) {
        ((float4*)(out + (size_t)BS * NA * 5))[i] = make_float4(0.f, 0.f, 0.f, 0.f);
    }
}

// ---------------------------------------------------------------------------
// K3b: per-anchor fast path (count<=1) + multi-anchor worklist compression.
// ---------------------------------------------------------------------------
__global__ void k_out(const int* __restrict__ gt_labels,
                      const float* __restrict__ gt_boxes,
                      float* __restrict__ out) {
    int idx = blockIdx.x * blockDim.x + threadIdx.x;
    if (idx >= BS * NA) return;
    int b = idx / NA;

    int c = g_count[idx];
    if (c > 1) {
        int pos = atomicAdd(&g_wcount, 1);
        g_wlist[pos] = idx;
        return;   // outputs written by k_resolve
    }
    int am = 0;
    float msk = 0.0f;
    if (c == 1) { am = g_am[idx]; msk = 1.0f; }

    int lbl = (msk > 0.0f) ? gt_labels[b * NM + am] : NC;

    float* tl = out;
    float* tb = out + (size_t)BS * NA;
    float* ts = out + (size_t)BS * NA * 5;
    float* mo = out + (size_t)BS * NA * 85;

    tl[idx] = (float)lbl;
    ((float4*)tb)[idx] = ((const float4*)gt_boxes)[b * NM + am];
    if (lbl < NC) ts[(size_t)idx * NC + lbl] = 1.0f;
    mo[idx] = msk;
}

// ---------------------------------------------------------------------------
// K4: one warp per multi anchor. argmax_m IoU over ALL 128 gts
// (first m on ties) via packed-key shfl reduction; lane 0 emits outputs.
// ---------------------------------------------------------------------------
__global__ void k_resolve(const float* __restrict__ pd_boxes,
                          const int* __restrict__ gt_labels,
                          const float* __restrict__ gt_boxes,
                          float* __restrict__ out) {
    int lane = threadIdx.x & 31;
    int warp = (blockIdx.x * blockDim.x + threadIdx.x) >> 5;
    int nwarps = (gridDim.x * blockDim.x) >> 5;
    int wc = g_wcount;

    for (int e = warp; e < wc; e += nwarps) {
        int idx = g_wlist[e];
        int b = idx / NA;
        float4 p = ((const float4*)pd_boxes)[idx];
        float area_p = (p.z - p.x) * (p.w - p.y);
        const float4* gb = (const float4*)gt_boxes + (size_t)b * NM;

        ull best = 0;
#pragma unroll
        for (int i = 0; i < NM / 32; ++i) {
            int m = lane + i * 32;
            float4 g = gb[m];
            float lx = fmaxf(g.x, p.x), ly = fmaxf(g.y, p.y);
            float rx = fminf(g.z, p.z), ry = fminf(g.w, p.w);
            float iw = fmaxf(rx - lx, 0.0f), ih = fmaxf(ry - ly, 0.0f);
            float inter = iw * ih;
            float area_g = (g.z - g.x) * (g.w - g.y);
            float iou = inter / (area_g + area_p - inter + EPSF);
            ull key = ((ull)__float_as_uint(iou) << 32) | (unsigned)(~(unsigned)m);
            if (key > best) best = key;
        }
#pragma unroll
        for (int off = 16; off > 0; off >>= 1) {
            ull o = __shfl_xor_sync(0xFFFFFFFFu, best, off);
            if (o > best) best = o;
        }
        if (lane == 0) {
            int am = (int)(~(unsigned)(best & 0xFFFFFFFFull));
            int lbl = gt_labels[b * NM + am];
            float* tl = out;
            float* tb = out + (size_t)BS * NA;
            float* ts = out + (size_t)BS * NA * 5;
            float* mo = out + (size_t)BS * NA * 85;
            tl[idx] = (float)lbl;
            ((float4*)tb)[idx] = ((const float4*)gt_boxes)[b * NM + am];
            if (lbl < NC) ts[(size_t)idx * NC + lbl] = 1.0f;
            mo[idx] = 1.0f;
        }
    }
}

// ---------------------------------------------------------------------------
extern "C" void kernel_launch(void* const* d_in, const int* in_sizes, int n_in,
                              void* d_out, int out_size) {
    const float* pd_scores = (const float*)d_in[0];
    const float* pd_boxes  = (const float*)d_in[1];
    const int*   gt_labels = (const int*)d_in[2];
    const float* gt_boxes  = (const float*)d_in[3];
    const float* mask_gt   = (const float*)d_in[4];
    float* out = (float*)d_out;

    int n = BS * NA;
    k_argmax_init<<<(n + 7) / 8, 256>>>(pd_scores);
    k_topk<<<BS * NM / G, 512>>>(pd_boxes, gt_boxes, mask_gt);
    int n4 = BS * NA * NC / 4;
    k_fill<<<(n4 + 255) / 256, 256>>>(out);
    k_out<<<(n + 255) / 256, 256>>>(gt_labels, gt_boxes, out);
    k_resolve<<<296, 256>>>(pd_boxes, gt_labels, gt_boxes, out);
}